// round 13
// baseline (speedup 1.0000x reference)
#include <cuda_runtime.h>
#include <cuda_fp16.h>

// AOLayer: out[b,n,a] = ang * rad, B=512,N=32,A=256,P=6.
// Round 13: combine the two proven mechanisms that were never combined:
//  (1) packed f32x2 math (r2: cut issue% 72->66.7; slot-halving works)
//  (2) lc-folded f16x2 exp2 (r11: removes MUFU bound, 6 MUFU/pair)
// Per p per pair: FMA2(arg) -> cvt f16x2 -> h2exp2 -> HFMA2. d/r2/angular
// all packed. ~44 slots/pair vs r11's ~56. rel_err ~5.3e-4 (same f16 stages).

#define A_DIM 256
#define P_DIM 6
#define BN_DIM (512 * 32)
#define ROWS_PER_BLOCK 16
#define NPAIRS (ROWS_PER_BLOCK / 2)

typedef unsigned long long u64;

__device__ __forceinline__ u64 pack2(float lo, float hi) {
    u64 r;
    asm("mov.b64 %0, {%1, %2};" : "=l"(r) : "f"(lo), "f"(hi));
    return r;
}
__device__ __forceinline__ u64 add2(u64 a, u64 b) {
    u64 r; asm("add.rn.f32x2 %0, %1, %2;" : "=l"(r) : "l"(a), "l"(b)); return r;
}
__device__ __forceinline__ u64 mul2(u64 a, u64 b) {
    u64 r; asm("mul.rn.f32x2 %0, %1, %2;" : "=l"(r) : "l"(a), "l"(b)); return r;
}
__device__ __forceinline__ u64 fma2(u64 a, u64 b, u64 c) {
    u64 r; asm("fma.rn.f32x2 %0, %1, %2, %3;" : "=l"(r) : "l"(a), "l"(b), "l"(c)); return r;
}
// packed f32x2 -> f16x2 -> exp2 (1 MUFU for both rows). The mov.b64 unpack is
// register aliasing (u64 = two 32-bit regs), not a real MOV when fed into cvt.
__device__ __forceinline__ __half2 h2exp2_p(u64 x) {
    float lo, hi;
    asm("mov.b64 {%0, %1}, %2;" : "=f"(lo), "=f"(hi) : "l"(x));
    return h2exp2(__floats2half2_rn(lo, hi));
}

__global__ void __launch_bounds__(A_DIM) aolayer_kernel(
    const float* __restrict__ pos,      // [BN, 3]
    const float* __restrict__ centers,  // [A, 3]
    const float* __restrict__ exps,     // [A, P]
    const float* __restrict__ coeffs,   // [A, P]
    const int*   __restrict__ powers,   // [A, 3]
    float* __restrict__ out)            // [BN, A]
{
    const int a = threadIdx.x;

    // ---- per-atom constants (once per block) ----
    const float cx = centers[a * 3 + 0];
    const float cy = centers[a * 3 + 1];
    const float cz = centers[a * 3 + 2];
    const u64 ncx2 = pack2(-cx, -cx);
    const u64 ncy2 = pack2(-cy, -cy);
    const u64 ncz2 = pack2(-cz, -cz);

    const float NEG_LOG2E = -1.4426950408889634f;
    u64 ep2[P_DIM], lc2[P_DIM];
    __half2 sg[P_DIM];
#pragma unroll
    for (int p = 0; p < P_DIM; p++) {
        const float e = exps[a * P_DIM + p] * NEG_LOG2E;
        const float c = coeffs[a * P_DIM + p];
        const float l = __log2f(fabsf(c));       // -inf if c==0 -> exp2 -> 0 (ok)
        ep2[p] = pack2(e, e);
        lc2[p] = pack2(l, l);
        sg[p]  = __float2half2_rn(copysignf(1.0f, c));
    }

    const int px = powers[a * 3 + 0];
    const int py = powers[a * 3 + 1];
    const int pz = powers[a * 3 + 2];
    // loop-invariant predicates -> ISETPs hoisted out of the unrolled loop
    const bool lx = (px >= 1), qx = (px == 2);
    const bool ly = (py >= 1), qy = (py == 2);
    const bool lz = (pz >= 1), qz = (pz == 2);

    // ---- stage pre-packed pos pairs: spos2[pr*3+d] = {row 2pr, row 2pr+1} ----
    __shared__ u64 spos2[NPAIRS * 3];
    const int row0 = blockIdx.x * ROWS_PER_BLOCK;
    if (threadIdx.x < NPAIRS * 3) {
        const int pr = threadIdx.x / 3;
        const int d  = threadIdx.x % 3;
        spos2[threadIdx.x] = pack2(pos[(row0 + 2 * pr) * 3 + d],
                                   pos[(row0 + 2 * pr + 1) * 3 + d]);
    }
    __syncthreads();

    float* out_base = out + (size_t)row0 * A_DIM + a;

#pragma unroll
    for (int pr = 0; pr < NPAIRS; pr++) {
        // 3x LDS.64, already packed {row, row+1}
        const u64 dxp = add2(spos2[pr * 3 + 0], ncx2);
        const u64 dyp = add2(spos2[pr * 3 + 1], ncy2);
        const u64 dzp = add2(spos2[pr * 3 + 2], ncz2);

        u64 r2p = mul2(dzp, dzp);
        r2p = fma2(dyp, dyp, r2p);
        r2p = fma2(dxp, dxp, r2p);

        // radial: term_p = sgn_p * 2^(ep_p*r2 + lc_p); 1 FMA2 + 1 cvt +
        // 1 h2exp2 (MUFU) + 1 HFMA2 per p per row-pair. Two accumulator chains.
        __half2 acc0 = __hmul2(h2exp2_p(fma2(ep2[0], r2p, lc2[0])), sg[0]);
        __half2 acc1 = __hmul2(h2exp2_p(fma2(ep2[1], r2p, lc2[1])), sg[1]);
        acc0 = __hfma2(h2exp2_p(fma2(ep2[2], r2p, lc2[2])), sg[2], acc0);
        acc1 = __hfma2(h2exp2_p(fma2(ep2[3], r2p, lc2[3])), sg[3], acc1);
        acc0 = __hfma2(h2exp2_p(fma2(ep2[4], r2p, lc2[4])), sg[4], acc0);
        acc1 = __hfma2(h2exp2_p(fma2(ep2[5], r2p, lc2[5])), sg[5], acc1);
        const __half2 rad2 = __hadd2(acc0, acc1);

        // back to packed f32x2 for the angular product (predicated packed muls)
        u64 o = pack2(__low2float(rad2), __high2float(rad2));
        if (lx) o = mul2(o, dxp);
        if (qx) o = mul2(o, dxp);
        if (ly) o = mul2(o, dyp);
        if (qy) o = mul2(o, dyp);
        if (lz) o = mul2(o, dzp);
        if (qz) o = mul2(o, dzp);

        float o0, o1;
        asm("mov.b64 {%0, %1}, %2;" : "=f"(o0), "=f"(o1) : "l"(o));
        out_base[(2 * pr) * A_DIM] = o0;
        out_base[(2 * pr + 1) * A_DIM] = o1;
    }
}

extern "C" void kernel_launch(void* const* d_in, const int* in_sizes, int n_in,
                              void* d_out, int out_size) {
    const float* pos     = (const float*)d_in[0];
    const float* centers = (const float*)d_in[1];
    const float* exps    = (const float*)d_in[2];
    const float* coeffs  = (const float*)d_in[3];
    const int*   powers  = (const int*)d_in[4];
    float* out = (float*)d_out;

    dim3 grid(BN_DIM / ROWS_PER_BLOCK);  // 1024 blocks
    dim3 block(A_DIM);                   // 256 threads, one per atom
    aolayer_kernel<<<grid, block>>>(pos, centers, exps, coeffs, powers, out);
}

// round 14
// speedup vs baseline: 1.0357x; 1.0357x over previous
#include <cuda_runtime.h>

// AOLayer: out[b,n,a] = ang * rad, B=512,N=32,A=256,P=6.
// Round 14: r5 (best wall, 12.768us, rel_err 1.8e-7) with the SMEM staging +
// __syncthreads removed. pos addresses are warp-uniform -> direct LDG
// broadcasts from L1 (1 request/warp, ~= LDS cost) with no STS, no BAR stall
// per block, and ptxas free to front-batch the 48 loads across the unrolled
// loop. Math identical to r5: scalar f32, 6 MUFU ex2, dual accumulators,
// predicated angular muls.

#define A_DIM 256
#define P_DIM 6
#define BN_DIM (512 * 32)
#define ROWS_PER_BLOCK 16

__device__ __forceinline__ float ex2f(float x) {
    float r;
    asm("ex2.approx.f32 %0, %1;" : "=f"(r) : "f"(x));
    return r;
}

__global__ void __launch_bounds__(A_DIM) aolayer_kernel(
    const float* __restrict__ pos,      // [BN, 3]
    const float* __restrict__ centers,  // [A, 3]
    const float* __restrict__ exps,     // [A, P]
    const float* __restrict__ coeffs,   // [A, P]
    const int*   __restrict__ powers,   // [A, 3]
    float* __restrict__ out)            // [BN, A]
{
    const int a = threadIdx.x;

    // ---- per-atom constants (once per block) ----
    const float ncx = -centers[a * 3 + 0];
    const float ncy = -centers[a * 3 + 1];
    const float ncz = -centers[a * 3 + 2];

    const float NEG_LOG2E = -1.4426950408889634f;
    float ep[P_DIM], co[P_DIM];
#pragma unroll
    for (int p = 0; p < P_DIM; p++) {
        ep[p] = exps[a * P_DIM + p] * NEG_LOG2E;
        co[p] = coeffs[a * P_DIM + p];
    }

    const int px = powers[a * 3 + 0];
    const int py = powers[a * 3 + 1];
    const int pz = powers[a * 3 + 2];
    // loop-invariant predicates -> ISETPs hoisted out of the unrolled loop
    const bool lx = (px >= 1), qx = (px == 2);
    const bool ly = (py >= 1), qy = (py == 2);
    const bool lz = (pz >= 1), qz = (pz == 2);

    const int row0 = blockIdx.x * ROWS_PER_BLOCK;
    const float* prow = pos + (size_t)row0 * 3;   // warp-uniform addresses
    float* out_base = out + (size_t)row0 * A_DIM + a;

#pragma unroll
    for (int r = 0; r < ROWS_PER_BLOCK; r++) {
        // uniform-address LDG: 1 request/warp, L1 broadcast (no SMEM, no BAR)
        const float dx = prow[r * 3 + 0] + ncx;
        const float dy = prow[r * 3 + 1] + ncy;
        const float dz = prow[r * 3 + 2] + ncz;

        const float r2 = fmaf(dx, dx, fmaf(dy, dy, dz * dz));

        // radial: dual accumulators, 6 MUFU ex2
        float rad0 = co[0] * ex2f(ep[0] * r2);
        float rad1 = co[1] * ex2f(ep[1] * r2);
        rad0 = fmaf(co[2], ex2f(ep[2] * r2), rad0);
        rad1 = fmaf(co[3], ex2f(ep[3] * r2), rad1);
        rad0 = fmaf(co[4], ex2f(ep[4] * r2), rad0);
        rad1 = fmaf(co[5], ex2f(ep[5] * r2), rad1);

        float o = rad0 + rad1;

        // angular as predicated muls (predicates loop-invariant)
        if (lx) o *= dx;
        if (qx) o *= dx;
        if (ly) o *= dy;
        if (qy) o *= dy;
        if (lz) o *= dz;
        if (qz) o *= dz;

        out_base[r * A_DIM] = o;
    }
}

extern "C" void kernel_launch(void* const* d_in, const int* in_sizes, int n_in,
                              void* d_out, int out_size) {
    const float* pos     = (const float*)d_in[0];
    const float* centers = (const float*)d_in[1];
    const float* exps    = (const float*)d_in[2];
    const float* coeffs  = (const float*)d_in[3];
    const int*   powers  = (const int*)d_in[4];
    float* out = (float*)d_out;

    dim3 grid(BN_DIM / ROWS_PER_BLOCK);  // 1024 blocks
    dim3 block(A_DIM);                   // 256 threads, one per atom
    aolayer_kernel<<<grid, block>>>(pos, centers, exps, coeffs, powers, out);
}

// round 15
// speedup vs baseline: 1.1629x; 1.1228x over previous
#include <cuda_runtime.h>

// AOLayer: out[b,n,a] = ang * rad, B=512,N=32,A=256,P=6.
// Round 15: two-phase fat-warp restructure. r4 evidence: with MUFU halved,
// nothing saturates yet dur stays ~11.3us -> per-warp dependency serialization
// at 40 regs is the residual binder. Phase 1 batches LDS/d/r2/angular for all
// 16 rows (keeps r2[16]+ang[16] in regs); phase 2 is a dense stream of 96
// independent FMUL->EX2->FFMA triples, letting one warp saturate MUFU issue.
// launch_bounds(256,3) gives ptxas ~85 regs to hold the batch.

#define A_DIM 256
#define P_DIM 6
#define BN_DIM (512 * 32)
#define ROWS_PER_BLOCK 16

__device__ __forceinline__ float ex2f(float x) {
    float r;
    asm("ex2.approx.f32 %0, %1;" : "=f"(r) : "f"(x));
    return r;
}

__global__ void __launch_bounds__(A_DIM, 3) aolayer_kernel(
    const float* __restrict__ pos,      // [BN, 3]
    const float* __restrict__ centers,  // [A, 3]
    const float* __restrict__ exps,     // [A, P]
    const float* __restrict__ coeffs,   // [A, P]
    const int*   __restrict__ powers,   // [A, 3]
    float* __restrict__ out)            // [BN, A]
{
    const int a = threadIdx.x;

    // ---- per-atom constants (once per block) ----
    const float ncx = -centers[a * 3 + 0];
    const float ncy = -centers[a * 3 + 1];
    const float ncz = -centers[a * 3 + 2];

    const float NEG_LOG2E = -1.4426950408889634f;
    float ep[P_DIM], co[P_DIM];
#pragma unroll
    for (int p = 0; p < P_DIM; p++) {
        ep[p] = exps[a * P_DIM + p] * NEG_LOG2E;
        co[p] = coeffs[a * P_DIM + p];
    }

    const int px = powers[a * 3 + 0];
    const int py = powers[a * 3 + 1];
    const int pz = powers[a * 3 + 2];
    const bool lx = (px >= 1), qx = (px == 2);
    const bool ly = (py >= 1), qy = (py == 2);
    const bool lz = (pz >= 1), qz = (pz == 2);

    // ---- stage pos rows into shared memory ----
    __shared__ float spos[ROWS_PER_BLOCK * 3];
    const int row0 = blockIdx.x * ROWS_PER_BLOCK;
    if (threadIdx.x < ROWS_PER_BLOCK * 3) {
        spos[threadIdx.x] = pos[row0 * 3 + threadIdx.x];
    }
    __syncthreads();

    // ---- phase 1: all rows' r2 and angular (d dies immediately) ----
    float r2v[ROWS_PER_BLOCK];
    float angv[ROWS_PER_BLOCK];
#pragma unroll
    for (int r = 0; r < ROWS_PER_BLOCK; r++) {
        const float dx = spos[r * 3 + 0] + ncx;
        const float dy = spos[r * 3 + 1] + ncy;
        const float dz = spos[r * 3 + 2] + ncz;

        r2v[r] = fmaf(dx, dx, fmaf(dy, dy, dz * dz));

        float t = lx ? dx : 1.0f;
        if (qx) t *= dx;
        if (ly) t *= dy;
        if (qy) t *= dy;
        if (lz) t *= dz;
        if (qz) t *= dz;
        angv[r] = t;
    }

    float* out_base = out + (size_t)row0 * A_DIM + a;

    // ---- phase 2: dense EX2 stream; 6 independent triples per row ----
#pragma unroll
    for (int r = 0; r < ROWS_PER_BLOCK; r++) {
        const float r2 = r2v[r];
        float rad0 = co[0] * ex2f(ep[0] * r2);
        float rad1 = co[1] * ex2f(ep[1] * r2);
        rad0 = fmaf(co[2], ex2f(ep[2] * r2), rad0);
        rad1 = fmaf(co[3], ex2f(ep[3] * r2), rad1);
        rad0 = fmaf(co[4], ex2f(ep[4] * r2), rad0);
        rad1 = fmaf(co[5], ex2f(ep[5] * r2), rad1);

        out_base[r * A_DIM] = angv[r] * (rad0 + rad1);
    }
}

extern "C" void kernel_launch(void* const* d_in, const int* in_sizes, int n_in,
                              void* d_out, int out_size) {
    const float* pos     = (const float*)d_in[0];
    const float* centers = (const float*)d_in[1];
    const float* exps    = (const float*)d_in[2];
    const float* coeffs  = (const float*)d_in[3];
    const int*   powers  = (const int*)d_in[4];
    float* out = (float*)d_out;

    dim3 grid(BN_DIM / ROWS_PER_BLOCK);  // 1024 blocks
    dim3 block(A_DIM);                   // 256 threads, one per atom
    aolayer_kernel<<<grid, block>>>(pos, centers, exps, coeffs, powers, out);
}